// round 4
// baseline (speedup 1.0000x reference)
#include <cuda_runtime.h>
#include <math.h>

#define BDIM 8192
#define FDIM 1024
#define EDIM 30
#define HDIM 256
#define CDIM 100
#define GDIM 4096
#define EPSV 1e-8f

#define TB 64
#define BK 16
#define NT (FDIM/BK)
#define A_STRIDE 68
#define A_TILE (BK*A_STRIDE)
#define B_TILE (BK*HDIM)
#define HS_STRIDE 260
#define HS_OFF (2*A_TILE + 2*B_TILE)
#define SMEM_FLOATS (HS_OFF + TB*HS_STRIDE)
#define MAXT 160
#define NTHR 512

__device__ int   g_assign[BDIM];
__device__ int   g_counts[EDIM];
__device__ int   g_cursor[EDIM];
__device__ float g_escale[EDIM];
__device__ int   g_sorted[BDIM];

__device__ __forceinline__ float warp_sum(float v){
  #pragma unroll
  for (int o=16;o>0;o>>=1) v += __shfl_xor_sync(0xffffffffu, v, o);
  return v;
}

// ---- packed fp32x2 helpers (sm_103a FFMA2: only reachable via PTX) ----
typedef unsigned long long u64;

__device__ __forceinline__ u64 pk(float lo, float hi){
  u64 r; asm("mov.b64 %0, {%1, %2};" : "=l"(r) : "f"(lo), "f"(hi)); return r;
}
__device__ __forceinline__ u64 pk2(float v){
  u64 r; asm("mov.b64 %0, {%1, %1};" : "=l"(r) : "f"(v)); return r;
}
__device__ __forceinline__ void upk(u64 p, float& lo, float& hi){
  asm("mov.b64 {%0, %1}, %2;" : "=f"(lo), "=f"(hi) : "l"(p));
}
__device__ __forceinline__ void ffma2(u64& d, u64 a, u64 b){
  asm("fma.rn.f32x2 %0, %1, %2, %0;" : "+l"(d) : "l"(a), "l"(b));
}

// ---------------------------------------------------------------------------
// K1: per-expert routing scale  escale[e] = align[e]*capacity[e]/(||p_e||+eps)
//     also zeroes histogram + scatter cursors. One block, 30 warps.
// ---------------------------------------------------------------------------
__global__ void prep_kernel(const float* __restrict__ protos,
                            const float* __restrict__ gnew,
                            const float* __restrict__ gmem,
                            const int*   __restrict__ class_counts){
  int warp = threadIdx.x >> 5;
  int lane = threadIdx.x & 31;
  if (threadIdx.x < EDIM){ g_counts[threadIdx.x] = 0; g_cursor[threadIdx.x] = 0; }
  if (warp >= EDIM) return;
  float d = 0.f, m2 = 0.f, n2 = 0.f;
  for (int i = lane; i < GDIM; i += 32){
    float a = gmem[(size_t)warp*GDIM + i];
    float b = gnew[i];
    d += a*b; m2 += a*a; n2 += b*b;
  }
  d = warp_sum(d); m2 = warp_sum(m2); n2 = warp_sum(n2);
  float p2 = 0.f;
  for (int f = lane; f < FDIM; f += 32){
    float p = protos[(size_t)warp*FDIM + f];
    p2 += p*p;
  }
  p2 = warp_sum(p2);
  if (lane == 0){
    float align = 0.5f*(1.0f + d/((sqrtf(m2)+EPSV)*(sqrtf(n2)+EPSV)));
    float over  = fmaxf((float)class_counts[warp]/5.0f - 1.0f, 0.0f);
    float cap   = expf(-1.5f*over);
    g_escale[warp] = align*cap/(sqrtf(p2)+EPSV);
  }
}

// ---------------------------------------------------------------------------
// K2: routing argmax. One warp per sample, x row cached in registers.
// ---------------------------------------------------------------------------
__global__ void route_kernel(const float* __restrict__ x,
                             const float* __restrict__ protos){
  int gw   = (int)((blockIdx.x*blockDim.x + threadIdx.x) >> 5);
  int lane = threadIdx.x & 31;
  if (gw >= BDIM) return;
  const float4* xr = (const float4*)(x + (size_t)gw*FDIM);
  float4 xv[8];
  #pragma unroll
  for (int q=0;q<8;q++) xv[q] = xr[lane + 32*q];
  float best = -3.4e38f; int bi = 0;
  for (int e=0;e<EDIM;e++){
    const float4* p = (const float4*)(protos + (size_t)e*FDIM);
    float s = 0.f;
    #pragma unroll
    for (int q=0;q<8;q++){
      float4 pv = __ldg(&p[lane + 32*q]);
      s += xv[q].x*pv.x + xv[q].y*pv.y + xv[q].z*pv.z + xv[q].w*pv.w;
    }
    s = warp_sum(s);
    s *= g_escale[e];
    if (s > best){ best = s; bi = e; }     // strict > == argmax first-index tiebreak
  }
  if (lane == 0){
    g_assign[gw] = bi;
    atomicAdd(&g_counts[bi], 1);
  }
}

// ---------------------------------------------------------------------------
// K3: scatter sample ids into expert-sorted order.
//     Each block recomputes the 30-entry prefix locally (no plan kernel).
// ---------------------------------------------------------------------------
__global__ void scatter_kernel(){
  __shared__ int base[EDIM];
  if (threadIdx.x == 0){
    int off = 0;
    #pragma unroll
    for (int e=0;e<EDIM;e++){ base[e] = off; off += g_counts[e]; }
  }
  __syncthreads();
  int b = blockIdx.x*blockDim.x + threadIdx.x;
  if (b < BDIM){
    int e = g_assign[b];
    int pos = base[e] + atomicAdd(&g_cursor[e], 1);
    g_sorted[pos] = b;
  }
}

// ---------------------------------------------------------------------------
// K4: per-tile  GEMM1 (64x1024 @ 1024x256) -> LN -> GELU(erf) -> GEMM2 -> out
//     512 threads (4 warps/SMSP), 4x8 micro-tiles, FFMA2, double-buffered smem.
// ---------------------------------------------------------------------------
__global__ __launch_bounds__(NTHR, 1) void mlp_kernel(
    const float* __restrict__ x,  const float* __restrict__ W1,
    const float* __restrict__ b1, const float* __restrict__ gamma,
    const float* __restrict__ beta, const float* __restrict__ W2,
    const float* __restrict__ b2, float* __restrict__ out)
{
  extern __shared__ float sm[];
  __shared__ int ridx[TB];
  __shared__ int s_meta[3];   // e, row0, nvalid

  const int t  = threadIdx.x;
  const int tx = t & 31;
  const int wy = t >> 5;      // warp 0..15

  // per-block tile lookup: walk expert histogram (30 iters, 1 thread)
  if (t == 0){
    int off = 0, tcum = 0, e = -1, row0 = 0, nv = 0;
    #pragma unroll 1
    for (int ee=0; ee<EDIM; ee++){
      int n  = g_counts[ee];
      int nt = (n + TB - 1) / TB;
      if (e < 0 && (int)blockIdx.x < tcum + nt){
        int li = (int)blockIdx.x - tcum;
        e = ee; row0 = off + li*TB;
        nv = n - li*TB; if (nv > TB) nv = TB;
      }
      tcum += nt; off += n;
    }
    s_meta[0] = e; s_meta[1] = row0; s_meta[2] = nv;
  }
  __syncthreads();
  const int e      = s_meta[0];
  const int row0   = s_meta[1];
  const int nvalid = s_meta[2];
  if (e < 0) return;

  if (t < TB){
    int li = (t < nvalid) ? (row0 + t) : row0;
    ridx[t] = g_sorted[li];
  }
  __syncthreads();

  const float* W1e = W1 + (size_t)e*FDIM*HDIM;

  // A staging: first 256 threads, one float4 each
  const int arow = (t & 255) >> 2;
  const int akk  = (t & 3) << 2;
  const float* aptr = x + (size_t)ridx[arow]*FDIM + akk;

  // B staging: all 512 threads, two float4 each
  int brow[2], bcol[2];
  #pragma unroll
  for (int i=0;i<2;i++){ int fid = t + NTHR*i; brow[i] = fid >> 6; bcol[i] = (fid & 63) << 2; }

  // prologue: load + stage k-tile 0 into buffer 0
  float4 aReg = make_float4(0.f,0.f,0.f,0.f);
  if (t < 256) aReg = *(const float4*)aptr;
  float4 bReg[2];
  #pragma unroll
  for (int i=0;i<2;i++) bReg[i] = *(const float4*)(W1e + (size_t)brow[i]*HDIM + bcol[i]);
  {
    if (t < 256){
      float* Ad = sm;
      Ad[(akk+0)*A_STRIDE + arow] = aReg.x;
      Ad[(akk+1)*A_STRIDE + arow] = aReg.y;
      Ad[(akk+2)*A_STRIDE + arow] = aReg.z;
      Ad[(akk+3)*A_STRIDE + arow] = aReg.w;
    }
    float* Bd = sm + 2*A_TILE;
    #pragma unroll
    for (int i=0;i<2;i++) *(float4*)&Bd[brow[i]*HDIM + bcol[i]] = bReg[i];
  }
  __syncthreads();

  // packed accumulators: 4 rows (4*wy..+3) x 8 cols (4tx..+3, 128+4tx..+3)
  u64 accp[4][4];
  #pragma unroll
  for (int i=0;i<4;i++)
    #pragma unroll
    for (int j=0;j<4;j++) accp[i][j] = 0ull;

  int buf = 0;
  for (int kt=0; kt<NT; ++kt){
    if (kt+1 < NT){
      if (t < 256) aReg = *(const float4*)(aptr + (kt+1)*BK);
      const float* wb = W1e + (size_t)(kt+1)*BK*HDIM;
      #pragma unroll
      for (int i=0;i<2;i++) bReg[i] = *(const float4*)(wb + (size_t)brow[i]*HDIM + bcol[i]);
    }
    const float* Ac = sm + buf*A_TILE;
    const float* Bc = sm + 2*A_TILE + buf*B_TILE;
    #pragma unroll
    for (int kk=0; kk<BK; ++kk){
      float4 a0 = *(const float4*)&Ac[kk*A_STRIDE + 4*wy];
      float4 bl = *(const float4*)&Bc[kk*HDIM + 4*tx];
      float4 bh = *(const float4*)&Bc[kk*HDIM + 128 + 4*tx];
      u64 bp0 = pk(bl.x, bl.y), bp1 = pk(bl.z, bl.w);
      u64 bp2 = pk(bh.x, bh.y), bp3 = pk(bh.z, bh.w);
      float av[4] = {a0.x,a0.y,a0.z,a0.w};
      #pragma unroll
      for (int i=0;i<4;i++){
        u64 ad = pk2(av[i]);
        ffma2(accp[i][0], ad, bp0);
        ffma2(accp[i][1], ad, bp1);
        ffma2(accp[i][2], ad, bp2);
        ffma2(accp[i][3], ad, bp3);
      }
    }
    if (kt+1 < NT){
      int nb = buf ^ 1;
      if (t < 256){
        float* Ad = sm + nb*A_TILE;
        Ad[(akk+0)*A_STRIDE + arow] = aReg.x;
        Ad[(akk+1)*A_STRIDE + arow] = aReg.y;
        Ad[(akk+2)*A_STRIDE + arow] = aReg.z;
        Ad[(akk+3)*A_STRIDE + arow] = aReg.w;
      }
      float* Bd = sm + 2*A_TILE + nb*B_TILE;
      #pragma unroll
      for (int i=0;i<2;i++) *(float4*)&Bd[brow[i]*HDIM + bcol[i]] = bReg[i];
      __syncthreads();
      buf = nb;
    }
  }

  // epilogue 1: += b1, stage h into smem
  float* hsp = sm + HS_OFF;
  {
    float4 blo = *(const float4*)&b1[e*HDIM + 4*tx];
    float4 bhi = *(const float4*)&b1[e*HDIM + 128 + 4*tx];
    float bb[8] = {blo.x,blo.y,blo.z,blo.w,bhi.x,bhi.y,bhi.z,bhi.w};
    #pragma unroll
    for (int i=0;i<4;i++){
      int r = 4*wy + i;
      float c0,c1,c2,c3,c4,c5,c6,c7;
      upk(accp[i][0], c0, c1); upk(accp[i][1], c2, c3);
      upk(accp[i][2], c4, c5); upk(accp[i][3], c6, c7);
      float4 lo = make_float4(c0+bb[0], c1+bb[1], c2+bb[2], c3+bb[3]);
      float4 hi = make_float4(c4+bb[4], c5+bb[5], c6+bb[6], c7+bb[7]);
      *(float4*)&hsp[r*HS_STRIDE + 4*tx]       = lo;
      *(float4*)&hsp[r*HS_STRIDE + 128 + 4*tx] = hi;
    }
  }
  __syncthreads();

  // LayerNorm + exact-erf GELU, warp per 4 rows
  {
    float4 glo = *(const float4*)&gamma[e*HDIM + 4*tx];
    float4 ghi = *(const float4*)&gamma[e*HDIM + 128 + 4*tx];
    float4 tlo = *(const float4*)&beta[e*HDIM + 4*tx];
    float4 thi = *(const float4*)&beta[e*HDIM + 128 + 4*tx];
    float gv[8]  = {glo.x,glo.y,glo.z,glo.w,ghi.x,ghi.y,ghi.z,ghi.w};
    float btv[8] = {tlo.x,tlo.y,tlo.z,tlo.w,thi.x,thi.y,thi.z,thi.w};
    #pragma unroll
    for (int rr=0; rr<4; ++rr){
      int r = wy*4 + rr;
      float4 v0 = *(float4*)&hsp[r*HS_STRIDE + 4*tx];
      float4 v1 = *(float4*)&hsp[r*HS_STRIDE + 128 + 4*tx];
      float vv[8] = {v0.x,v0.y,v0.z,v0.w,v1.x,v1.y,v1.z,v1.w};
      float s = 0.f, s2 = 0.f;
      #pragma unroll
      for (int k=0;k<8;k++){ s += vv[k]; s2 += vv[k]*vv[k]; }
      s = warp_sum(s); s2 = warp_sum(s2);
      float mu   = s  * (1.0f/HDIM);
      float var  = s2 * (1.0f/HDIM) - mu*mu;
      float rstd = rsqrtf(var + 1e-5f);
      #pragma unroll
      for (int k=0;k<8;k++){
        float ln = (vv[k]-mu)*rstd*gv[k] + btv[k];
        vv[k] = 0.5f*ln*(1.0f + erff(ln*0.70710678118654752f));
      }
      *(float4*)&hsp[r*HS_STRIDE + 4*tx]       = make_float4(vv[0],vv[1],vv[2],vv[3]);
      *(float4*)&hsp[r*HS_STRIDE + 128 + 4*tx] = make_float4(vv[4],vv[5],vv[6],vv[7]);
    }
  }
  __syncthreads();

  // GEMM2: [64x256] @ W2[256x100] (padded to 128 cols), K-chunked through smem
  u64 acc2p[4][2];
  #pragma unroll
  for (int i=0;i<4;i++){ acc2p[i][0]=0ull; acc2p[i][1]=0ull; }

  float* w2s = sm;   // reuse GEMM1 A buffers (2176 floats >= 16*128)
  const float* W2e = W2 + (size_t)e*HDIM*CDIM;
  const int w2r = t >> 5;            // 0..15
  const int w2c = (t & 31) << 2;     // 0..124

  for (int kt=0; kt<HDIM/BK; ++kt){
    __syncthreads();
    {
      float4 v = make_float4(0.f,0.f,0.f,0.f);
      if (w2c < CDIM)
        v = *(const float4*)&W2e[(size_t)(kt*BK + w2r)*CDIM + w2c];
      *(float4*)&w2s[w2r*128 + w2c] = v;
    }
    __syncthreads();
    #pragma unroll
    for (int kq=0; kq<BK/4; ++kq){
      float4 ak[4];
      #pragma unroll
      for (int i=0;i<4;i++){
        int r = 4*wy + i;
        ak[i] = *(const float4*)&hsp[r*HS_STRIDE + kt*BK + 4*kq];
      }
      #pragma unroll
      for (int q=0; q<4; ++q){
        int kk = 4*kq + q;
        float4 b = *(const float4*)&w2s[kk*128 + 4*tx];
        u64 b0 = pk(b.x, b.y), b1p = pk(b.z, b.w);
        #pragma unroll
        for (int i=0;i<4;i++){
          float a = (q==0)?ak[i].x:(q==1)?ak[i].y:(q==2)?ak[i].z:ak[i].w;
          u64 ad = pk2(a);
          ffma2(acc2p[i][0], ad, b0);
          ffma2(acc2p[i][1], ad, b1p);
        }
      }
    }
  }

  // epilogue 2: += b2, scatter rows to their original sample slots
  if (4*tx < CDIM){   // tx <= 24 covers cols 0..99
    float4 b2v = *(const float4*)&b2[e*CDIM + 4*tx];
    #pragma unroll
    for (int i=0;i<4;i++){
      int r = 4*wy + i;
      if (r < nvalid){
        int sdx = ridx[r];
        float o0,o1,o2,o3;
        upk(acc2p[i][0], o0, o1); upk(acc2p[i][1], o2, o3);
        float4 o = make_float4(o0+b2v.x, o1+b2v.y, o2+b2v.z, o3+b2v.w);
        *(float4*)&out[(size_t)sdx*CDIM + 4*tx] = o;
      }
    }
  }
}

// ---------------------------------------------------------------------------
extern "C" void kernel_launch(void* const* d_in, const int* in_sizes, int n_in,
                              void* d_out, int out_size){
  const float* x      = (const float*)d_in[0];
  const float* protos = (const float*)d_in[1];
  const float* gnew   = (const float*)d_in[2];
  const float* gmem   = (const float*)d_in[3];
  const int*   cc     = (const int*)  d_in[4];
  const float* W1     = (const float*)d_in[5];
  const float* b1     = (const float*)d_in[6];
  const float* gamma  = (const float*)d_in[7];
  const float* beta   = (const float*)d_in[8];
  const float* W2     = (const float*)d_in[9];
  const float* b2     = (const float*)d_in[10];
  float* out = (float*)d_out;

  prep_kernel<<<1, 960>>>(protos, gnew, gmem, cc);
  route_kernel<<<BDIM/8, 256>>>(x, protos);
  scatter_kernel<<<BDIM/256, 256>>>();

  size_t smem_bytes = SMEM_FLOATS * sizeof(float);
  cudaFuncSetAttribute(mlp_kernel, cudaFuncAttributeMaxDynamicSharedMemorySize, (int)smem_bytes);
  mlp_kernel<<<MAXT, NTHR, smem_bytes>>>(x, W1, b1, gamma, beta, W2, b2, out);
}

// round 5
// speedup vs baseline: 1.0249x; 1.0249x over previous
#include <cuda_runtime.h>
#include <math.h>

#define BDIM 8192
#define FDIM 1024
#define EDIM 30
#define HDIM 256
#define CDIM 100
#define GDIM 4096
#define EPSV 1e-8f

#define TB 64
#define BK 16
#define NT (FDIM/BK)
#define A_STRIDE 68
#define A_TILE (BK*A_STRIDE)
#define B_TILE (BK*HDIM)
#define HS_STRIDE 260
#define HS_OFF (2*A_TILE + 2*B_TILE)
#define SMEM_FLOATS (HS_OFF + TB*HS_STRIDE)
#define MAXT 160
#define NTHR 512

__device__ int   g_assign[BDIM];
__device__ int   g_counts[EDIM];
__device__ int   g_cursor[EDIM];
__device__ float g_escale[EDIM];
__device__ int   g_sorted[BDIM];

__device__ __forceinline__ float warp_sum(float v){
  #pragma unroll
  for (int o=16;o>0;o>>=1) v += __shfl_xor_sync(0xffffffffu, v, o);
  return v;
}

// ---- packed fp32x2 helpers (sm_103a FFMA2: only reachable via PTX) ----
typedef unsigned long long u64;

__device__ __forceinline__ u64 pk(float lo, float hi){
  u64 r; asm("mov.b64 %0, {%1, %2};" : "=l"(r) : "f"(lo), "f"(hi)); return r;
}
__device__ __forceinline__ u64 pk2(float v){
  u64 r; asm("mov.b64 %0, {%1, %1};" : "=l"(r) : "f"(v)); return r;
}
__device__ __forceinline__ void upk(u64 p, float& lo, float& hi){
  asm("mov.b64 {%0, %1}, %2;" : "=f"(lo), "=f"(hi) : "l"(p));
}
__device__ __forceinline__ void ffma2(u64& d, u64 a, u64 b){
  asm("fma.rn.f32x2 %0, %1, %2, %0;" : "+l"(d) : "l"(a), "l"(b));
}

// ---------------------------------------------------------------------------
// K1: per-expert routing scale  escale[e] = align[e]*capacity[e]/(||p_e||+eps)
// ---------------------------------------------------------------------------
__global__ void prep_kernel(const float* __restrict__ protos,
                            const float* __restrict__ gnew,
                            const float* __restrict__ gmem,
                            const int*   __restrict__ class_counts){
  int warp = threadIdx.x >> 5;
  int lane = threadIdx.x & 31;
  if (threadIdx.x < EDIM){ g_counts[threadIdx.x] = 0; g_cursor[threadIdx.x] = 0; }
  if (warp >= EDIM) return;
  float d = 0.f, m2 = 0.f, n2 = 0.f;
  for (int i = lane; i < GDIM; i += 32){
    float a = gmem[(size_t)warp*GDIM + i];
    float b = gnew[i];
    d += a*b; m2 += a*a; n2 += b*b;
  }
  d = warp_sum(d); m2 = warp_sum(m2); n2 = warp_sum(n2);
  float p2 = 0.f;
  for (int f = lane; f < FDIM; f += 32){
    float p = protos[(size_t)warp*FDIM + f];
    p2 += p*p;
  }
  p2 = warp_sum(p2);
  if (lane == 0){
    float align = 0.5f*(1.0f + d/((sqrtf(m2)+EPSV)*(sqrtf(n2)+EPSV)));
    float over  = fmaxf((float)class_counts[warp]/5.0f - 1.0f, 0.0f);
    float cap   = expf(-1.5f*over);
    g_escale[warp] = align*cap/(sqrtf(p2)+EPSV);
  }
}

// ---------------------------------------------------------------------------
// K2: routing argmax. One warp per sample, x row cached in registers.
// ---------------------------------------------------------------------------
__global__ void route_kernel(const float* __restrict__ x,
                             const float* __restrict__ protos){
  int gw   = (int)((blockIdx.x*blockDim.x + threadIdx.x) >> 5);
  int lane = threadIdx.x & 31;
  if (gw >= BDIM) return;
  const float4* xr = (const float4*)(x + (size_t)gw*FDIM);
  float4 xv[8];
  #pragma unroll
  for (int q=0;q<8;q++) xv[q] = xr[lane + 32*q];
  float best = -3.4e38f; int bi = 0;
  for (int e=0;e<EDIM;e++){
    const float4* p = (const float4*)(protos + (size_t)e*FDIM);
    float s = 0.f;
    #pragma unroll
    for (int q=0;q<8;q++){
      float4 pv = __ldg(&p[lane + 32*q]);
      s += xv[q].x*pv.x + xv[q].y*pv.y + xv[q].z*pv.z + xv[q].w*pv.w;
    }
    s = warp_sum(s);
    s *= g_escale[e];
    if (s > best){ best = s; bi = e; }     // strict > == argmax first-index tiebreak
  }
  if (lane == 0){
    g_assign[gw] = bi;
    atomicAdd(&g_counts[bi], 1);
  }
}

// ---------------------------------------------------------------------------
// K3: scatter sample ids into expert-sorted order (block-local prefix).
// ---------------------------------------------------------------------------
__global__ void scatter_kernel(){
  __shared__ int base[EDIM];
  if (threadIdx.x == 0){
    int off = 0;
    #pragma unroll
    for (int e=0;e<EDIM;e++){ base[e] = off; off += g_counts[e]; }
  }
  __syncthreads();
  int b = blockIdx.x*blockDim.x + threadIdx.x;
  if (b < BDIM){
    int e = g_assign[b];
    int pos = base[e] + atomicAdd(&g_cursor[e], 1);
    g_sorted[pos] = b;
  }
}

// ---------------------------------------------------------------------------
// K4: per-tile GEMM1 (64x1024 @ 1024x256) -> LN -> GELU(erf) -> GEMM2 -> out
//     512 threads, 8row x 4col micro-tiles with ROW-PAIR packed FFMA2:
//     A row pairs come straight from ulonglong2 LDS (zero pack instructions).
// ---------------------------------------------------------------------------
__global__ __launch_bounds__(NTHR, 1) void mlp_kernel(
    const float* __restrict__ x,  const float* __restrict__ W1,
    const float* __restrict__ b1, const float* __restrict__ gamma,
    const float* __restrict__ beta, const float* __restrict__ W2,
    const float* __restrict__ b2, float* __restrict__ out)
{
  extern __shared__ float sm[];
  __shared__ int ridx[TB];
  __shared__ int s_meta[3];   // e, row0, nvalid

  const int t  = threadIdx.x;
  const int tx = t & 31;
  const int w  = t >> 5;      // warp 0..15
  const int wr = w >> 1;      // row group 0..7  (rows 8*wr .. 8*wr+7)
  const int wc = w & 1;       // col group 0..1  (cols 128*wc + 4*tx .. +3)

  // per-block tile lookup: walk expert histogram (30 iters, 1 thread)
  if (t == 0){
    int off = 0, tcum = 0, e = -1, row0 = 0, nv = 0;
    #pragma unroll 1
    for (int ee=0; ee<EDIM; ee++){
      int n  = g_counts[ee];
      int nt = (n + TB - 1) / TB;
      if (e < 0 && (int)blockIdx.x < tcum + nt){
        int li = (int)blockIdx.x - tcum;
        e = ee; row0 = off + li*TB;
        nv = n - li*TB; if (nv > TB) nv = TB;
      }
      tcum += nt; off += n;
    }
    s_meta[0] = e; s_meta[1] = row0; s_meta[2] = nv;
  }
  __syncthreads();
  const int e      = s_meta[0];
  const int row0   = s_meta[1];
  const int nvalid = s_meta[2];
  if (e < 0) return;

  if (t < TB){
    int li = (t < nvalid) ? (row0 + t) : row0;
    ridx[t] = g_sorted[li];
  }
  __syncthreads();

  const float* W1e = W1 + (size_t)e*FDIM*HDIM;

  // A staging: first 256 threads, one float4 each
  const int arow = (t & 255) >> 2;
  const int akk  = (t & 3) << 2;
  const float* aptr = x + (size_t)ridx[arow]*FDIM + akk;

  // B staging: all 512 threads, two float4 each
  int brow[2], bcol[2];
  #pragma unroll
  for (int i=0;i<2;i++){ int fid = t + NTHR*i; brow[i] = fid >> 6; bcol[i] = (fid & 63) << 2; }

  // prologue: load + stage k-tile 0 into buffer 0
  float4 aReg = make_float4(0.f,0.f,0.f,0.f);
  if (t < 256) aReg = *(const float4*)aptr;
  float4 bReg[2];
  #pragma unroll
  for (int i=0;i<2;i++) bReg[i] = *(const float4*)(W1e + (size_t)brow[i]*HDIM + bcol[i]);
  {
    if (t < 256){
      float* Ad = sm;
      Ad[(akk+0)*A_STRIDE + arow] = aReg.x;
      Ad[(akk+1)*A_STRIDE + arow] = aReg.y;
      Ad[(akk+2)*A_STRIDE + arow] = aReg.z;
      Ad[(akk+3)*A_STRIDE + arow] = aReg.w;
    }
    float* Bd = sm + 2*A_TILE;
    #pragma unroll
    for (int i=0;i<2;i++) *(float4*)&Bd[brow[i]*HDIM + bcol[i]] = bReg[i];
  }
  __syncthreads();

  // packed accumulators: accp[rp][c] = (row 8wr+2rp, row 8wr+2rp+1) @ col 128wc+4tx+c
  u64 accp[4][4];
  #pragma unroll
  for (int i=0;i<4;i++)
    #pragma unroll
    for (int j=0;j<4;j++) accp[i][j] = 0ull;

  int buf = 0;
  for (int kt=0; kt<NT; ++kt){
    if (kt+1 < NT){
      if (t < 256) aReg = *(const float4*)(aptr + (kt+1)*BK);
      const float* wb = W1e + (size_t)(kt+1)*BK*HDIM;
      #pragma unroll
      for (int i=0;i<2;i++) bReg[i] = *(const float4*)(wb + (size_t)brow[i]*HDIM + bcol[i]);
    }
    const float* Ac = sm + buf*A_TILE;
    const float* Bc = sm + 2*A_TILE + buf*B_TILE;
    #pragma unroll
    for (int kk=0; kk<BK; ++kk){
      // A row pairs, directly packed by the 16B loads (rows contiguous per k)
      const float* Arow = &Ac[kk*A_STRIDE + 8*wr];
      ulonglong2 apl = *(const ulonglong2*)(Arow);      // (r0,r1),(r2,r3)
      ulonglong2 aph = *(const ulonglong2*)(Arow + 4);  // (r4,r5),(r6,r7)
      float4 b = *(const float4*)&Bc[kk*HDIM + 128*wc + 4*tx];
      u64 b0 = pk2(b.x), b1p = pk2(b.y), b2p = pk2(b.z), b3p = pk2(b.w);
      ffma2(accp[0][0], apl.x, b0);  ffma2(accp[0][1], apl.x, b1p);
      ffma2(accp[0][2], apl.x, b2p); ffma2(accp[0][3], apl.x, b3p);
      ffma2(accp[1][0], apl.y, b0);  ffma2(accp[1][1], apl.y, b1p);
      ffma2(accp[1][2], apl.y, b2p); ffma2(accp[1][3], apl.y, b3p);
      ffma2(accp[2][0], aph.x, b0);  ffma2(accp[2][1], aph.x, b1p);
      ffma2(accp[2][2], aph.x, b2p); ffma2(accp[2][3], aph.x, b3p);
      ffma2(accp[3][0], aph.y, b0);  ffma2(accp[3][1], aph.y, b1p);
      ffma2(accp[3][2], aph.y, b2p); ffma2(accp[3][3], aph.y, b3p);
    }
    if (kt+1 < NT){
      int nb = buf ^ 1;
      if (t < 256){
        float* Ad = sm + nb*A_TILE;
        Ad[(akk+0)*A_STRIDE + arow] = aReg.x;
        Ad[(akk+1)*A_STRIDE + arow] = aReg.y;
        Ad[(akk+2)*A_STRIDE + arow] = aReg.z;
        Ad[(akk+3)*A_STRIDE + arow] = aReg.w;
      }
      float* Bd = sm + 2*A_TILE + nb*B_TILE;
      #pragma unroll
      for (int i=0;i<2;i++) *(float4*)&Bd[brow[i]*HDIM + bcol[i]] = bReg[i];
      __syncthreads();
      buf = nb;
    }
  }

  // epilogue 1: += b1, stage h into smem
  float* hsp = sm + HS_OFF;
  {
    float4 bb = *(const float4*)&b1[e*HDIM + 128*wc + 4*tx];
    #pragma unroll
    for (int rp=0; rp<4; ++rp){
      int r0 = 8*wr + 2*rp;
      float x0,y0,x1,y1,x2,y2,x3,y3;
      upk(accp[rp][0], x0, y0); upk(accp[rp][1], x1, y1);
      upk(accp[rp][2], x2, y2); upk(accp[rp][3], x3, y3);
      *(float4*)&hsp[(r0  )*HS_STRIDE + 128*wc + 4*tx] =
          make_float4(x0+bb.x, x1+bb.y, x2+bb.z, x3+bb.w);
      *(float4*)&hsp[(r0+1)*HS_STRIDE + 128*wc + 4*tx] =
          make_float4(y0+bb.x, y1+bb.y, y2+bb.z, y3+bb.w);
    }
  }
  __syncthreads();

  // LayerNorm + exact-erf GELU, warp per 4 rows
  {
    float4 glo = *(const float4*)&gamma[e*HDIM + 4*tx];
    float4 ghi = *(const float4*)&gamma[e*HDIM + 128 + 4*tx];
    float4 tlo = *(const float4*)&beta[e*HDIM + 4*tx];
    float4 thi = *(const float4*)&beta[e*HDIM + 128 + 4*tx];
    float gv[8]  = {glo.x,glo.y,glo.z,glo.w,ghi.x,ghi.y,ghi.z,ghi.w};
    float btv[8] = {tlo.x,tlo.y,tlo.z,tlo.w,thi.x,thi.y,thi.z,thi.w};
    #pragma unroll
    for (int rr=0; rr<4; ++rr){
      int r = w*4 + rr;
      float4 v0 = *(float4*)&hsp[r*HS_STRIDE + 4*tx];
      float4 v1 = *(float4*)&hsp[r*HS_STRIDE + 128 + 4*tx];
      float vv[8] = {v0.x,v0.y,v0.z,v0.w,v1.x,v1.y,v1.z,v1.w};
      float s = 0.f, s2 = 0.f;
      #pragma unroll
      for (int k=0;k<8;k++){ s += vv[k]; s2 += vv[k]*vv[k]; }
      s = warp_sum(s); s2 = warp_sum(s2);
      float mu   = s  * (1.0f/HDIM);
      float var  = s2 * (1.0f/HDIM) - mu*mu;
      float rstd = rsqrtf(var + 1e-5f);
      #pragma unroll
      for (int k=0;k<8;k++){
        float ln = (vv[k]-mu)*rstd*gv[k] + btv[k];
        vv[k] = 0.5f*ln*(1.0f + erff(ln*0.70710678118654752f));
      }
      *(float4*)&hsp[r*HS_STRIDE + 4*tx]       = make_float4(vv[0],vv[1],vv[2],vv[3]);
      *(float4*)&hsp[r*HS_STRIDE + 128 + 4*tx] = make_float4(vv[4],vv[5],vv[6],vv[7]);
    }
  }
  __syncthreads();

  // GEMM2: [64x256] @ W2[256x100] (padded to 128 cols), K-chunked through smem
  u64 acc2p[4][2];
  #pragma unroll
  for (int i=0;i<4;i++){ acc2p[i][0]=0ull; acc2p[i][1]=0ull; }

  float* w2s = sm;   // reuse GEMM1 A buffers (2176 floats >= 16*128)
  const float* W2e = W2 + (size_t)e*HDIM*CDIM;
  const int w2r = t >> 5;            // 0..15
  const int w2c = (t & 31) << 2;     // 0..124

  for (int kt=0; kt<HDIM/BK; ++kt){
    __syncthreads();
    {
      float4 v = make_float4(0.f,0.f,0.f,0.f);
      if (w2c < CDIM)
        v = *(const float4*)&W2e[(size_t)(kt*BK + w2r)*CDIM + w2c];
      *(float4*)&w2s[w2r*128 + w2c] = v;
    }
    __syncthreads();
    #pragma unroll
    for (int kq=0; kq<BK/4; ++kq){
      float4 ak[4];
      #pragma unroll
      for (int i=0;i<4;i++){
        int r = 4*w + i;
        ak[i] = *(const float4*)&hsp[r*HS_STRIDE + kt*BK + 4*kq];
      }
      #pragma unroll
      for (int q=0; q<4; ++q){
        int kk = 4*kq + q;
        float4 b = *(const float4*)&w2s[kk*128 + 4*tx];
        u64 b0 = pk(b.x, b.y), b1p = pk(b.z, b.w);
        #pragma unroll
        for (int i=0;i<4;i++){
          float a = (q==0)?ak[i].x:(q==1)?ak[i].y:(q==2)?ak[i].z:ak[i].w;
          u64 ad = pk2(a);
          ffma2(acc2p[i][0], ad, b0);
          ffma2(acc2p[i][1], ad, b1p);
        }
      }
    }
  }

  // epilogue 2: += b2, scatter rows to their original sample slots
  if (4*tx < CDIM){   // tx <= 24 covers cols 0..99
    float4 b2v = *(const float4*)&b2[e*CDIM + 4*tx];
    #pragma unroll
    for (int i=0;i<4;i++){
      int r = 4*w + i;
      if (r < nvalid){
        int sdx = ridx[r];
        float o0,o1,o2,o3;
        upk(acc2p[i][0], o0, o1); upk(acc2p[i][1], o2, o3);
        float4 o = make_float4(o0+b2v.x, o1+b2v.y, o2+b2v.z, o3+b2v.w);
        *(float4*)&out[(size_t)sdx*CDIM + 4*tx] = o;
      }
    }
  }
}

// ---------------------------------------------------------------------------
extern "C" void kernel_launch(void* const* d_in, const int* in_sizes, int n_in,
                              void* d_out, int out_size){
  const float* x      = (const float*)d_in[0];
  const float* protos = (const float*)d_in[1];
  const float* gnew   = (const float*)d_in[2];
  const float* gmem   = (const float*)d_in[3];
  const int*   cc     = (const int*)  d_in[4];
  const float* W1     = (const float*)d_in[5];
  const float* b1     = (const float*)d_in[6];
  const float* gamma  = (const float*)d_in[7];
  const float* beta   = (const float*)d_in[8];
  const float* W2     = (const float*)d_in[9];
  const float* b2     = (const float*)d_in[10];
  float* out = (float*)d_out;

  prep_kernel<<<1, 960>>>(protos, gnew, gmem, cc);
  route_kernel<<<BDIM/8, 256>>>(x, protos);
  scatter_kernel<<<BDIM/256, 256>>>();

  size_t smem_bytes = SMEM_FLOATS * sizeof(float);
  cudaFuncSetAttribute(mlp_kernel, cudaFuncAttributeMaxDynamicSharedMemorySize, (int)smem_bytes);
  mlp_kernel<<<MAXT, NTHR, smem_bytes>>>(x, W1, b1, gamma, beta, W2, b2, out);
}

// round 6
// speedup vs baseline: 1.0571x; 1.0314x over previous
#include <cuda_runtime.h>
#include <math.h>

#define BDIM 8192
#define FDIM 1024
#define EDIM 30
#define HDIM 256
#define CDIM 100
#define GDIM 4096
#define EPSV 1e-8f

#define TB 64
#define BK 16
#define NT (FDIM/BK)
#define A_STRIDE 68
#define A_TILE (BK*A_STRIDE)
#define B_TILE (BK*HDIM)
#define HS_STRIDE 260
#define HS_OFF (2*A_TILE + 2*B_TILE)
#define SMEM_FLOATS (HS_OFF + TB*HS_STRIDE)
#define MAXT 160
#define NTHR 512

__device__ int   g_assign[BDIM];
__device__ int   g_counts[EDIM];
__device__ int   g_cursor[EDIM];
__device__ float g_escale[EDIM];
__device__ int   g_sorted[BDIM];

__device__ __forceinline__ float warp_sum(float v){
  #pragma unroll
  for (int o=16;o>0;o>>=1) v += __shfl_xor_sync(0xffffffffu, v, o);
  return v;
}

// ---- packed fp32x2 helpers (sm_103a FFMA2: only reachable via PTX) ----
typedef unsigned long long u64;

__device__ __forceinline__ u64 pk(float lo, float hi){
  u64 r; asm("mov.b64 %0, {%1, %2};" : "=l"(r) : "f"(lo), "f"(hi)); return r;
}
__device__ __forceinline__ u64 pk2(float v){
  u64 r; asm("mov.b64 %0, {%1, %1};" : "=l"(r) : "f"(v)); return r;
}
__device__ __forceinline__ void upk(u64 p, float& lo, float& hi){
  asm("mov.b64 {%0, %1}, %2;" : "=f"(lo), "=f"(hi) : "l"(p));
}
__device__ __forceinline__ void ffma2(u64& d, u64 a, u64 b){
  asm("fma.rn.f32x2 %0, %1, %2, %0;" : "+l"(d) : "l"(a), "l"(b));
}

// ---------------------------------------------------------------------------
// K1: per-expert routing scale  escale[e] = align[e]*capacity[e]/(||p_e||+eps)
// ---------------------------------------------------------------------------
__global__ void prep_kernel(const float* __restrict__ protos,
                            const float* __restrict__ gnew,
                            const float* __restrict__ gmem,
                            const int*   __restrict__ class_counts){
  int warp = threadIdx.x >> 5;
  int lane = threadIdx.x & 31;
  if (threadIdx.x < EDIM){ g_counts[threadIdx.x] = 0; g_cursor[threadIdx.x] = 0; }
  if (warp >= EDIM) return;
  float d = 0.f, m2 = 0.f, n2 = 0.f;
  for (int i = lane; i < GDIM; i += 32){
    float a = gmem[(size_t)warp*GDIM + i];
    float b = gnew[i];
    d += a*b; m2 += a*a; n2 += b*b;
  }
  d = warp_sum(d); m2 = warp_sum(m2); n2 = warp_sum(n2);
  float p2 = 0.f;
  for (int f = lane; f < FDIM; f += 32){
    float p = protos[(size_t)warp*FDIM + f];
    p2 += p*p;
  }
  p2 = warp_sum(p2);
  if (lane == 0){
    float align = 0.5f*(1.0f + d/((sqrtf(m2)+EPSV)*(sqrtf(n2)+EPSV)));
    float over  = fmaxf((float)class_counts[warp]/5.0f - 1.0f, 0.0f);
    float cap   = expf(-1.5f*over);
    g_escale[warp] = align*cap/(sqrtf(p2)+EPSV);
  }
}

// ---------------------------------------------------------------------------
// K2: routing argmax. One warp per sample, x row cached in registers.
// ---------------------------------------------------------------------------
__global__ void route_kernel(const float* __restrict__ x,
                             const float* __restrict__ protos){
  int gw   = (int)((blockIdx.x*blockDim.x + threadIdx.x) >> 5);
  int lane = threadIdx.x & 31;
  if (gw >= BDIM) return;
  const float4* xr = (const float4*)(x + (size_t)gw*FDIM);
  float4 xv[8];
  #pragma unroll
  for (int q=0;q<8;q++) xv[q] = xr[lane + 32*q];
  float best = -3.4e38f; int bi = 0;
  for (int e=0;e<EDIM;e++){
    const float4* p = (const float4*)(protos + (size_t)e*FDIM);
    float s = 0.f;
    #pragma unroll
    for (int q=0;q<8;q++){
      float4 pv = __ldg(&p[lane + 32*q]);
      s += xv[q].x*pv.x + xv[q].y*pv.y + xv[q].z*pv.z + xv[q].w*pv.w;
    }
    s = warp_sum(s);
    s *= g_escale[e];
    if (s > best){ best = s; bi = e; }     // strict > == argmax first-index tiebreak
  }
  if (lane == 0){
    g_assign[gw] = bi;
    atomicAdd(&g_counts[bi], 1);
  }
}

// ---------------------------------------------------------------------------
// K3: scatter sample ids into expert-sorted order (block-local prefix).
// ---------------------------------------------------------------------------
__global__ void scatter_kernel(){
  __shared__ int base[EDIM];
  if (threadIdx.x == 0){
    int off = 0;
    #pragma unroll
    for (int e=0;e<EDIM;e++){ base[e] = off; off += g_counts[e]; }
  }
  __syncthreads();
  int b = blockIdx.x*blockDim.x + threadIdx.x;
  if (b < BDIM){
    int e = g_assign[b];
    int pos = base[e] + atomicAdd(&g_cursor[e], 1);
    g_sorted[pos] = b;
  }
}

// ---------------------------------------------------------------------------
// K4: per-tile GEMM1 (64x1024 @ 1024x256) -> LN -> GELU(erf) -> GEMM2 -> out
//     512 threads, 8row x 4col micro-tiles with ROW-PAIR packed FFMA2:
//     A row pairs come straight from ulonglong2 LDS (zero pack instructions).
// ---------------------------------------------------------------------------
__global__ __launch_bounds__(NTHR, 1) void mlp_kernel(
    const float* __restrict__ x,  const float* __restrict__ W1,
    const float* __restrict__ b1, const float* __restrict__ gamma,
    const float* __restrict__ beta, const float* __restrict__ W2,
    const float* __restrict__ b2, float* __restrict__ out)
{
  extern __shared__ float sm[];
  __shared__ int ridx[TB];
  __shared__ int s_meta[3];   // e, row0, nvalid

  const int t  = threadIdx.x;
  const int tx = t & 31;
  const int w  = t >> 5;      // warp 0..15
  const int wr = w >> 1;      // row group 0..7  (rows 8*wr .. 8*wr+7)
  const int wc = w & 1;       // col group 0..1  (cols 128*wc + 4*tx .. +3)

  // per-block tile lookup: walk expert histogram (30 iters, 1 thread)
  if (t == 0){
    int off = 0, tcum = 0, e = -1, row0 = 0, nv = 0;
    #pragma unroll 1
    for (int ee=0; ee<EDIM; ee++){
      int n  = g_counts[ee];
      int nt = (n + TB - 1) / TB;
      if (e < 0 && (int)blockIdx.x < tcum + nt){
        int li = (int)blockIdx.x - tcum;
        e = ee; row0 = off + li*TB;
        nv = n - li*TB; if (nv > TB) nv = TB;
      }
      tcum += nt; off += n;
    }
    s_meta[0] = e; s_meta[1] = row0; s_meta[2] = nv;
  }
  __syncthreads();
  const int e      = s_meta[0];
  const int row0   = s_meta[1];
  const int nvalid = s_meta[2];
  if (e < 0) return;

  if (t < TB){
    int li = (t < nvalid) ? (row0 + t) : row0;
    ridx[t] = g_sorted[li];
  }
  __syncthreads();

  const float* W1e = W1 + (size_t)e*FDIM*HDIM;

  // A staging: first 256 threads, one float4 each
  const int arow = (t & 255) >> 2;
  const int akk  = (t & 3) << 2;
  const float* aptr = x + (size_t)ridx[arow]*FDIM + akk;

  // B staging: all 512 threads, two float4 each
  int brow[2], bcol[2];
  #pragma unroll
  for (int i=0;i<2;i++){ int fid = t + NTHR*i; brow[i] = fid >> 6; bcol[i] = (fid & 63) << 2; }

  // prologue: load + stage k-tile 0 into buffer 0
  float4 aReg = make_float4(0.f,0.f,0.f,0.f);
  if (t < 256) aReg = *(const float4*)aptr;
  float4 bReg[2];
  #pragma unroll
  for (int i=0;i<2;i++) bReg[i] = *(const float4*)(W1e + (size_t)brow[i]*HDIM + bcol[i]);
  {
    if (t < 256){
      float* Ad = sm;
      Ad[(akk+0)*A_STRIDE + arow] = aReg.x;
      Ad[(akk+1)*A_STRIDE + arow] = aReg.y;
      Ad[(akk+2)*A_STRIDE + arow] = aReg.z;
      Ad[(akk+3)*A_STRIDE + arow] = aReg.w;
    }
    float* Bd = sm + 2*A_TILE;
    #pragma unroll
    for (int i=0;i<2;i++) *(float4*)&Bd[brow[i]*HDIM + bcol[i]] = bReg[i];
  }
  __syncthreads();

  // packed accumulators: accp[rp][c] = (row 8wr+2rp, row 8wr+2rp+1) @ col 128wc+4tx+c
  u64 accp[4][4];
  #pragma unroll
  for (int i=0;i<4;i++)
    #pragma unroll
    for (int j=0;j<4;j++) accp[i][j] = 0ull;

  int buf = 0;
  for (int kt=0; kt<NT; ++kt){
    if (kt+1 < NT){
      if (t < 256) aReg = *(const float4*)(aptr + (kt+1)*BK);
      const float* wb = W1e + (size_t)(kt+1)*BK*HDIM;
      #pragma unroll
      for (int i=0;i<2;i++) bReg[i] = *(const float4*)(wb + (size_t)brow[i]*HDIM + bcol[i]);
    }
    const float* Ac = sm + buf*A_TILE;
    const float* Bc = sm + 2*A_TILE + buf*B_TILE;
    #pragma unroll
    for (int kk=0; kk<BK; ++kk){
      // A row pairs, directly packed by the 16B loads (rows contiguous per k)
      const float* Arow = &Ac[kk*A_STRIDE + 8*wr];
      ulonglong2 apl = *(const ulonglong2*)(Arow);      // (r0,r1),(r2,r3)
      ulonglong2 aph = *(const ulonglong2*)(Arow + 4);  // (r4,r5),(r6,r7)
      float4 b = *(const float4*)&Bc[kk*HDIM + 128*wc + 4*tx];
      u64 b0 = pk2(b.x), b1p = pk2(b.y), b2p = pk2(b.z), b3p = pk2(b.w);
      ffma2(accp[0][0], apl.x, b0);  ffma2(accp[0][1], apl.x, b1p);
      ffma2(accp[0][2], apl.x, b2p); ffma2(accp[0][3], apl.x, b3p);
      ffma2(accp[1][0], apl.y, b0);  ffma2(accp[1][1], apl.y, b1p);
      ffma2(accp[1][2], apl.y, b2p); ffma2(accp[1][3], apl.y, b3p);
      ffma2(accp[2][0], aph.x, b0);  ffma2(accp[2][1], aph.x, b1p);
      ffma2(accp[2][2], aph.x, b2p); ffma2(accp[2][3], aph.x, b3p);
      ffma2(accp[3][0], aph.y, b0);  ffma2(accp[3][1], aph.y, b1p);
      ffma2(accp[3][2], aph.y, b2p); ffma2(accp[3][3], aph.y, b3p);
    }
    if (kt+1 < NT){
      int nb = buf ^ 1;
      if (t < 256){
        float* Ad = sm + nb*A_TILE;
        Ad[(akk+0)*A_STRIDE + arow] = aReg.x;
        Ad[(akk+1)*A_STRIDE + arow] = aReg.y;
        Ad[(akk+2)*A_STRIDE + arow] = aReg.z;
        Ad[(akk+3)*A_STRIDE + arow] = aReg.w;
      }
      float* Bd = sm + 2*A_TILE + nb*B_TILE;
      #pragma unroll
      for (int i=0;i<2;i++) *(float4*)&Bd[brow[i]*HDIM + bcol[i]] = bReg[i];
      __syncthreads();
      buf = nb;
    }
  }

  // epilogue 1: += b1, stage h into smem
  float* hsp = sm + HS_OFF;
  {
    float4 bb = *(const float4*)&b1[e*HDIM + 128*wc + 4*tx];
    #pragma unroll
    for (int rp=0; rp<4; ++rp){
      int r0 = 8*wr + 2*rp;
      float x0,y0,x1,y1,x2,y2,x3,y3;
      upk(accp[rp][0], x0, y0); upk(accp[rp][1], x1, y1);
      upk(accp[rp][2], x2, y2); upk(accp[rp][3], x3, y3);
      *(float4*)&hsp[(r0  )*HS_STRIDE + 128*wc + 4*tx] =
          make_float4(x0+bb.x, x1+bb.y, x2+bb.z, x3+bb.w);
      *(float4*)&hsp[(r0+1)*HS_STRIDE + 128*wc + 4*tx] =
          make_float4(y0+bb.x, y1+bb.y, y2+bb.z, y3+bb.w);
    }
  }
  __syncthreads();

  // LayerNorm + exact-erf GELU, warp per 4 rows
  {
    float4 glo = *(const float4*)&gamma[e*HDIM + 4*tx];
    float4 ghi = *(const float4*)&gamma[e*HDIM + 128 + 4*tx];
    float4 tlo = *(const float4*)&beta[e*HDIM + 4*tx];
    float4 thi = *(const float4*)&beta[e*HDIM + 128 + 4*tx];
    float gv[8]  = {glo.x,glo.y,glo.z,glo.w,ghi.x,ghi.y,ghi.z,ghi.w};
    float btv[8] = {tlo.x,tlo.y,tlo.z,tlo.w,thi.x,thi.y,thi.z,thi.w};
    #pragma unroll
    for (int rr=0; rr<4; ++rr){
      int r = w*4 + rr;
      float4 v0 = *(float4*)&hsp[r*HS_STRIDE + 4*tx];
      float4 v1 = *(float4*)&hsp[r*HS_STRIDE + 128 + 4*tx];
      float vv[8] = {v0.x,v0.y,v0.z,v0.w,v1.x,v1.y,v1.z,v1.w};
      float s = 0.f, s2 = 0.f;
      #pragma unroll
      for (int k=0;k<8;k++){ s += vv[k]; s2 += vv[k]*vv[k]; }
      s = warp_sum(s); s2 = warp_sum(s2);
      float mu   = s  * (1.0f/HDIM);
      float var  = s2 * (1.0f/HDIM) - mu*mu;
      float rstd = rsqrtf(var + 1e-5f);
      #pragma unroll
      for (int k=0;k<8;k++){
        float ln = (vv[k]-mu)*rstd*gv[k] + btv[k];
        vv[k] = 0.5f*ln*(1.0f + erff(ln*0.70710678118654752f));
      }
      *(float4*)&hsp[r*HS_STRIDE + 4*tx]       = make_float4(vv[0],vv[1],vv[2],vv[3]);
      *(float4*)&hsp[r*HS_STRIDE + 128 + 4*tx] = make_float4(vv[4],vv[5],vv[6],vv[7]);
    }
  }
  __syncthreads();

  // GEMM2: [64x256] @ W2[256x100] (padded to 128 cols), K-chunked through smem
  u64 acc2p[4][2];
  #pragma unroll
  for (int i=0;i<4;i++){ acc2p[i][0]=0ull; acc2p[i][1]=0ull; }

  float* w2s = sm;   // reuse GEMM1 A buffers (2176 floats >= 16*128)
  const float* W2e = W2 + (size_t)e*HDIM*CDIM;
  const int w2r = t >> 5;            // 0..15
  const int w2c = (t & 31) << 2;     // 0..124

  for (int kt=0; kt<HDIM/BK; ++kt){
    __syncthreads();
    {
      float4 v = make_float4(0.f,0.f,0.f,0.f);
      if (w2c < CDIM)
        v = *(const float4*)&W2e[(size_t)(kt*BK + w2r)*CDIM + w2c];
      *(float4*)&w2s[w2r*128 + w2c] = v;
    }
    __syncthreads();
    #pragma unroll
    for (int kq=0; kq<BK/4; ++kq){
      float4 ak[4];
      #pragma unroll
      for (int i=0;i<4;i++){
        int r = 4*w + i;
        ak[i] = *(const float4*)&hsp[r*HS_STRIDE + kt*BK + 4*kq];
      }
      #pragma unroll
      for (int q=0; q<4; ++q){
        int kk = 4*kq + q;
        float4 b = *(const float4*)&w2s[kk*128 + 4*tx];
        u64 b0 = pk(b.x, b.y), b1p = pk(b.z, b.w);
        #pragma unroll
        for (int i=0;i<4;i++){
          float a = (q==0)?ak[i].x:(q==1)?ak[i].y:(q==2)?ak[i].z:ak[i].w;
          u64 ad = pk2(a);
          ffma2(acc2p[i][0], ad, b0);
          ffma2(acc2p[i][1], ad, b1p);
        }
      }
    }
  }

  // epilogue 2: += b2, scatter rows to their original sample slots
  if (4*tx < CDIM){   // tx <= 24 covers cols 0..99
    float4 b2v = *(const float4*)&b2[e*CDIM + 4*tx];
    #pragma unroll
    for (int i=0;i<4;i++){
      int r = 4*w + i;
      if (r < nvalid){
        int sdx = ridx[r];
        float o0,o1,o2,o3;
        upk(acc2p[i][0], o0, o1); upk(acc2p[i][1], o2, o3);
        float4 o = make_float4(o0+b2v.x, o1+b2v.y, o2+b2v.z, o3+b2v.w);
        *(float4*)&out[(size_t)sdx*CDIM + 4*tx] = o;
      }
    }
  }
}

// ---------------------------------------------------------------------------
extern "C" void kernel_launch(void* const* d_in, const int* in_sizes, int n_in,
                              void* d_out, int out_size){
  const float* x      = (const float*)d_in[0];
  const float* protos = (const float*)d_in[1];
  const float* gnew   = (const float*)d_in[2];
  const float* gmem   = (const float*)d_in[3];
  const int*   cc     = (const int*)  d_in[4];
  const float* W1     = (const float*)d_in[5];
  const float* b1     = (const float*)d_in[6];
  const float* gamma  = (const float*)d_in[7];
  const float* beta   = (const float*)d_in[8];
  const float* W2     = (const float*)d_in[9];
  const float* b2     = (const float*)d_in[10];
  float* out = (float*)d_out;

  prep_kernel<<<1, 960>>>(protos, gnew, gmem, cc);
  route_kernel<<<BDIM/8, 256>>>(x, protos);
  scatter_kernel<<<BDIM/256, 256>>>();

  size_t smem_bytes = SMEM_FLOATS * sizeof(float);
  cudaFuncSetAttribute(mlp_kernel, cudaFuncAttributeMaxDynamicSharedMemorySize, (int)smem_bytes);
  mlp_kernel<<<MAXT, NTHR, smem_bytes>>>(x, W1, b1, gamma, beta, W2, b2, out);
}

// round 8
// speedup vs baseline: 1.5296x; 1.4470x over previous
#include <cuda_runtime.h>
#include <cuda_bf16.h>
#include <math.h>
#include <stdint.h>

#define BDIM 8192
#define FDIM 1024
#define EDIM 30
#define HDIM 256
#define CDIM 100
#define GDIM 4096
#define EPSV 1e-8f

#define TBR  64
#define NTHR 512
#define MAXT 160
#define NC1  32      /* 1024/32 k-chunks GEMM1 */
#define NC2  8       /* 256/32  k-chunks GEMM2 */

/* ---- dynamic smem layout (bytes) ---- */
#define LDW    80        /* row stride A1/B1/B2: 40 bf16 */
#define A1HL   5120      /* A1 hi->lo  (64*80)   */
#define A1BUF  10240
#define B1HL   20480     /* B1 hi->lo  (256*80)  */
#define B1BUF  40960
#define A1_OFF 0
#define B1_OFF 20480
#define PSUM_OFF 102400
#define PSQ_OFF  104448
#define MURS_OFF 106496
#define PARB1  107008
#define PARGM  108032
#define PARBT  109056
#define PARB2  110080
#define A2_OFF 110592
#define A2HL   33792     /* 64*528 */
#define LDA2   528
#define B2_OFF 178176
#define B2HL   10240     /* 128*80 */
#define B2BUF  20480
#define DYNB   219136

__device__ int   g_assign[BDIM];
__device__ int   g_counts[EDIM];
__device__ int   g_cursor[EDIM];
__device__ float g_escale[EDIM];
__device__ int   g_sorted[BDIM];

__device__ __forceinline__ float warp_sum(float v){
  #pragma unroll
  for (int o=16;o>0;o>>=1) v += __shfl_xor_sync(0xffffffffu, v, o);
  return v;
}

__device__ __forceinline__ uint32_t smem_u32(const void* p){
  uint32_t a;
  asm("{ .reg .u64 t; cvta.to.shared.u64 t, %1; cvt.u32.u64 %0, t; }" : "=r"(a) : "l"(p));
  return a;
}

__device__ __forceinline__ void split2(float v0, float v1, uint32_t& hi, uint32_t& lo){
  __nv_bfloat16 h0 = __float2bfloat16(v0), h1 = __float2bfloat16(v1);
  float r0 = v0 - __bfloat162float(h0), r1 = v1 - __bfloat162float(h1);
  __nv_bfloat162 hp; hp.x = h0; hp.y = h1;
  __nv_bfloat162 lp = __floats2bfloat162_rn(r0, r1);
  hi = *(uint32_t*)&hp; lo = *(uint32_t*)&lp;
}

__device__ __forceinline__ void ldsm4(uint32_t* r, uint32_t a){
  asm volatile("ldmatrix.sync.aligned.m8n8.x4.shared.b16 {%0,%1,%2,%3}, [%4];"
    : "=r"(r[0]),"=r"(r[1]),"=r"(r[2]),"=r"(r[3]) : "r"(a));
}
__device__ __forceinline__ void mma_bf16(float* d, const uint32_t* a, uint32_t b0, uint32_t b1){
  asm volatile("mma.sync.aligned.m16n8k16.row.col.f32.bf16.bf16.f32 "
    "{%0,%1,%2,%3}, {%4,%5,%6,%7}, {%8,%9}, {%0,%1,%2,%3};"
    : "+f"(d[0]),"+f"(d[1]),"+f"(d[2]),"+f"(d[3])
    : "r"(a[0]),"r"(a[1]),"r"(a[2]),"r"(a[3]), "r"(b0),"r"(b1));
}
__device__ __forceinline__ float gelu(float v){
  return 0.5f*v*(1.0f + erff(v*0.70710678118654752f));
}

// ---------------------------------------------------------------------------
__global__ void prep_kernel(const float* __restrict__ protos,
                            const float* __restrict__ gnew,
                            const float* __restrict__ gmem,
                            const int*   __restrict__ class_counts){
  int warp = threadIdx.x >> 5;
  int lane = threadIdx.x & 31;
  if (threadIdx.x < EDIM){ g_counts[threadIdx.x] = 0; g_cursor[threadIdx.x] = 0; }
  if (warp >= EDIM) return;
  float d = 0.f, m2 = 0.f, n2 = 0.f;
  for (int i = lane; i < GDIM; i += 32){
    float a = gmem[(size_t)warp*GDIM + i];
    float b = gnew[i];
    d += a*b; m2 += a*a; n2 += b*b;
  }
  d = warp_sum(d); m2 = warp_sum(m2); n2 = warp_sum(n2);
  float p2 = 0.f;
  for (int f = lane; f < FDIM; f += 32){
    float p = protos[(size_t)warp*FDIM + f];
    p2 += p*p;
  }
  p2 = warp_sum(p2);
  if (lane == 0){
    float align = 0.5f*(1.0f + d/((sqrtf(m2)+EPSV)*(sqrtf(n2)+EPSV)));
    float over  = fmaxf((float)class_counts[warp]/5.0f - 1.0f, 0.0f);
    float cap   = expf(-1.5f*over);
    g_escale[warp] = align*cap/(sqrtf(p2)+EPSV);
  }
}

__global__ void route_kernel(const float* __restrict__ x,
                             const float* __restrict__ protos){
  int gw   = (int)((blockIdx.x*blockDim.x + threadIdx.x) >> 5);
  int lane = threadIdx.x & 31;
  if (gw >= BDIM) return;
  const float4* xr = (const float4*)(x + (size_t)gw*FDIM);
  float4 xv[8];
  #pragma unroll
  for (int q=0;q<8;q++) xv[q] = xr[lane + 32*q];
  float best = -3.4e38f; int bi = 0;
  for (int e=0;e<EDIM;e++){
    const float4* p = (const float4*)(protos + (size_t)e*FDIM);
    float s = 0.f;
    #pragma unroll
    for (int q=0;q<8;q++){
      float4 pv = __ldg(&p[lane + 32*q]);
      s += xv[q].x*pv.x + xv[q].y*pv.y + xv[q].z*pv.z + xv[q].w*pv.w;
    }
    s = warp_sum(s);
    s *= g_escale[e];
    if (s > best){ best = s; bi = e; }
  }
  if (lane == 0){
    g_assign[gw] = bi;
    atomicAdd(&g_counts[bi], 1);
  }
}

__global__ void scatter_kernel(){
  __shared__ int base[EDIM];
  if (threadIdx.x == 0){
    int off = 0;
    #pragma unroll
    for (int e=0;e<EDIM;e++){ base[e] = off; off += g_counts[e]; }
  }
  __syncthreads();
  int b = blockIdx.x*blockDim.x + threadIdx.x;
  if (b < BDIM){
    int e = g_assign[b];
    int pos = base[e] + atomicAdd(&g_cursor[e], 1);
    g_sorted[pos] = b;
  }
}

// ---------------------------------------------------------------------------
// MLP via bf16 split-precision mma.sync (HMMA fallback path on sm_103):
// per 64-row tile: GEMM1(64x1024 @ 1024x256) -> LN -> GELU -> GEMM2 -> scatter
// ---------------------------------------------------------------------------
__global__ __launch_bounds__(NTHR, 1)
void mlp_kernel(const float* __restrict__ x,  const float* __restrict__ W1,
                const float* __restrict__ b1, const float* __restrict__ gamma,
                const float* __restrict__ beta, const float* __restrict__ W2,
                const float* __restrict__ b2, float* __restrict__ out)
{
  extern __shared__ __align__(128) char smc[];
  __shared__ int ridx[TBR];
  __shared__ int s_meta[3];

  const int t    = threadIdx.x;
  const int lane = t & 31;
  const int w    = t >> 5;        // 0..15
  const int wm   = w >> 3;        // GEMM1 m-group (0..1): rows 32*wm
  const int wn   = w & 7;         // GEMM1 n-group (0..7): cols 32*wn

  if (t == 0){
    int off = 0, tcum = 0, e = -1, row0 = 0, nv = 0;
    #pragma unroll 1
    for (int ee=0; ee<EDIM; ee++){
      int n  = g_counts[ee];
      int nt = (n + TBR - 1) / TBR;
      if (e < 0 && (int)blockIdx.x < tcum + nt){
        int li = (int)blockIdx.x - tcum;
        e = ee; row0 = off + li*TBR;
        nv = n - li*TBR; if (nv > TBR) nv = TBR;
      }
      tcum += nt; off += n;
    }
    s_meta[0] = e; s_meta[1] = row0; s_meta[2] = nv;
  }
  __syncthreads();
  const int e      = s_meta[0];
  const int row0   = s_meta[1];
  const int nvalid = s_meta[2];
  if (e < 0) return;

  if (t < TBR){
    int li = (t < nvalid) ? (row0 + t) : row0;
    ridx[t] = g_sorted[li];
  }
  float* b1s = (float*)(smc + PARB1);
  float* gms = (float*)(smc + PARGM);
  float* bts = (float*)(smc + PARBT);
  float* b2s = (float*)(smc + PARB2);
  if (t < HDIM){
    b1s[t] = b1[e*HDIM + t];
    gms[t] = gamma[e*HDIM + t];
    bts[t] = beta[e*HDIM + t];
  }
  if (t >= HDIM && t < HDIM+128){
    int c = t - HDIM;
    b2s[c] = (c < CDIM) ? b2[e*CDIM + c] : 0.f;
  }
  __syncthreads();

  const uint32_t smb = smem_u32(smc);
  const float* W1e = W1 + (size_t)e*FDIM*HDIM;
  const float* W2e = W2 + (size_t)e*HDIM*CDIM;
  const float* xrow = x + (size_t)ridx[t>>3]*FDIM + (t&7)*4;

  // B1 conversion mapping (conflict-free STS): per pass p: n = p*128 + w*8 + (lane&7)
  const int bn0 = w*8 + (lane&7);
  const int kp0 = lane >> 3;

  // ---- stage chunk 0 ----
  {
    float4 v = *(const float4*)xrow;
    uint32_t h0,l0,h1,l1;
    split2(v.x,v.y,h0,l0); split2(v.z,v.w,h1,l1);
    char* Ad = smc + A1_OFF;
    *(uint2*)(Ad + (t>>3)*LDW + (t&7)*8)        = make_uint2(h0,h1);
    *(uint2*)(Ad + A1HL + (t>>3)*LDW + (t&7)*8) = make_uint2(l0,l1);
    char* Bd = smc + B1_OFF;
    #pragma unroll
    for (int p=0;p<2;p++){
      int n = p*128 + bn0;
      #pragma unroll
      for (int i=0;i<4;i++){
        int kp = i*4 + kp0;
        float v0 = W1e[(size_t)(2*kp)*HDIM + n];
        float v1 = W1e[(size_t)(2*kp+1)*HDIM + n];
        uint32_t hi, lo; split2(v0,v1,hi,lo);
        *(uint32_t*)(Bd + n*LDW + kp*4)        = hi;
        *(uint32_t*)(Bd + B1HL + n*LDW + kp*4) = lo;
      }
    }
  }
  __syncthreads();

  float acc1[2][4][4];
  #pragma unroll
  for (int mt=0;mt<2;mt++)
    #pragma unroll
    for (int nt=0;nt<4;nt++)
      #pragma unroll
      for (int q=0;q<4;q++) acc1[mt][nt][q] = 0.f;

  int buf = 0;
  #pragma unroll 1
  for (int kt=0; kt<NC1; ++kt){
    float4 pa; float2 pb[8];
    const bool more = (kt+1 < NC1);
    if (more){
      pa = *(const float4*)(xrow + (kt+1)*32);
      const float* Wb = W1e + (size_t)(kt+1)*32*HDIM;
      #pragma unroll
      for (int p=0;p<2;p++){
        int n = p*128 + bn0;
        #pragma unroll
        for (int i=0;i<4;i++){
          int kp = i*4 + kp0;
          pb[p*4+i].x = Wb[(size_t)(2*kp)*HDIM + n];
          pb[p*4+i].y = Wb[(size_t)(2*kp+1)*HDIM + n];
        }
      }
    }
    // ---- compute on buf ----
    {
      uint32_t ah[2][2][4], al[2][2][4];
      const uint32_t Ab = smb + A1_OFF + buf*A1BUF;
      #pragma unroll
      for (int mt=0;mt<2;mt++)
        #pragma unroll
        for (int kg=0;kg<2;kg++){
          uint32_t ad = Ab + (wm*32 + mt*16 + (lane&15))*LDW + kg*32 + (lane>>4)*16;
          ldsm4(ah[mt][kg], ad);
          ldsm4(al[mt][kg], ad + A1HL);
        }
      const uint32_t Bb = smb + B1_OFF + buf*B1BUF;
      #pragma unroll
      for (int nt=0;nt<4;nt++){
        uint32_t ba = Bb + (wn*32 + nt*8 + (lane&7))*LDW + (lane>>3)*16;
        uint32_t bh[4], bl[4];
        ldsm4(bh, ba);
        ldsm4(bl, ba + B1HL);
        #pragma unroll
        for (int mt=0;mt<2;mt++)
          #pragma unroll
          for (int kg=0;kg<2;kg++){
            mma_bf16(acc1[mt][nt], ah[mt][kg], bh[2*kg], bh[2*kg+1]);
            mma_bf16(acc1[mt][nt], ah[mt][kg], bl[2*kg], bl[2*kg+1]);
            mma_bf16(acc1[mt][nt], al[mt][kg], bh[2*kg], bh[2*kg+1]);
          }
      }
    }
    // ---- convert + store next chunk ----
    if (more){
      int nb = buf ^ 1;
      uint32_t h0,l0,h1,l1;
      split2(pa.x,pa.y,h0,l0); split2(pa.z,pa.w,h1,l1);
      char* Ad = smc + A1_OFF + nb*A1BUF;
      *(uint2*)(Ad + (t>>3)*LDW + (t&7)*8)        = make_uint2(h0,h1);
      *(uint2*)(Ad + A1HL + (t>>3)*LDW + (t&7)*8) = make_uint2(l0,l1);
      char* Bd = smc + B1_OFF + nb*B1BUF;
      #pragma unroll
      for (int p=0;p<2;p++){
        int n = p*128 + bn0;
        #pragma unroll
        for (int i=0;i<4;i++){
          int kp = i*4 + kp0;
          uint32_t hi, lo; split2(pb[p*4+i].x, pb[p*4+i].y, hi, lo);
          *(uint32_t*)(Bd + n*LDW + kp*4)        = hi;
          *(uint32_t*)(Bd + B1HL + n*LDW + kp*4) = lo;
        }
      }
      __syncthreads();
      buf = nb;
    }
  }

  // ---- + b1, LN stats ----
  float* psum = (float*)(smc + PSUM_OFF);
  float* psq  = (float*)(smc + PSQ_OFF);
  #pragma unroll
  for (int mt=0;mt<2;mt++)
    #pragma unroll
    for (int nt=0;nt<4;nt++)
      #pragma unroll
      for (int q=0;q<4;q++){
        int c = wn*32 + nt*8 + 2*(lane&3) + (q&1);
        acc1[mt][nt][q] += b1s[c];
      }
  #pragma unroll
  for (int mt=0;mt<2;mt++)
    #pragma unroll
    for (int qh=0;qh<2;qh++){
      float s = 0.f, s2 = 0.f;
      #pragma unroll
      for (int nt=0;nt<4;nt++)
        #pragma unroll
        for (int ql=0;ql<2;ql++){
          float v = acc1[mt][nt][2*qh+ql];
          s += v; s2 += v*v;
        }
      s  += __shfl_xor_sync(0xffffffffu, s, 1);  s  += __shfl_xor_sync(0xffffffffu, s, 2);
      s2 += __shfl_xor_sync(0xffffffffu, s2, 1); s2 += __shfl_xor_sync(0xffffffffu, s2, 2);
      if ((lane & 3) == 0){
        int r = wm*32 + mt*16 + qh*8 + (lane>>2);
        psum[r*8 + wn] = s;
        psq [r*8 + wn] = s2;
      }
    }
  __syncthreads();
  if (t < TBR){
    float S = 0.f, S2 = 0.f;
    #pragma unroll
    for (int j=0;j<8;j++){ S += psum[t*8+j]; S2 += psq[t*8+j]; }
    float mu   = S * (1.0f/HDIM);
    float var  = S2 * (1.0f/HDIM) - mu*mu;
    float rstd = rsqrtf(var + 1e-5f);
    ((float2*)(smc + MURS_OFF))[t] = make_float2(mu, rstd);
  }
  __syncthreads();

  // ---- normalize + GELU -> A2 (bf16 hi/lo, [64][264]) ----
  {
    const float2* murs = (const float2*)(smc + MURS_OFF);
    #pragma unroll
    for (int mt=0;mt<2;mt++)
      #pragma unroll
      for (int qh=0;qh<2;qh++){
        int r = wm*32 + mt*16 + qh*8 + (lane>>2);
        float2 ms = murs[r];
        #pragma unroll
        for (int nt=0;nt<4;nt++){
          int c0 = wn*32 + nt*8 + 2*(lane&3);
          float g0 = gelu((acc1[mt][nt][2*qh+0]-ms.x)*ms.y*gms[c0]   + bts[c0]);
          float g1 = gelu((acc1[mt][nt][2*qh+1]-ms.x)*ms.y*gms[c0+1] + bts[c0+1]);
          uint32_t hi, lo; split2(g0, g1, hi, lo);
          *(uint32_t*)(smc + A2_OFF + r*LDA2 + c0*2)        = hi;
          *(uint32_t*)(smc + A2_OFF + A2HL + r*LDA2 + c0*2) = lo;
        }
      }
  }

  // ---- stage B2 chunk 0 ----
  {
    char* Bd = smc + B2_OFF;
    int n = bn0 + ((w>=16)?0:0);
    n = w*8 + (lane&7);           // 0..127
    #pragma unroll
    for (int i=0;i<4;i++){
      int kp = i*4 + kp0;
      float v0 = 0.f, v1 = 0.f;
      if (n < CDIM){
        v0 = W2e[(size_t)(2*kp)*CDIM + n];
        v1 = W2e[(size_t)(2*kp+1)*CDIM + n];
      }
      uint32_t hi, lo; split2(v0,v1,hi,lo);
      *(uint32_t*)(Bd + n*LDW + kp*4)        = hi;
      *(uint32_t*)(Bd + B2HL + n*LDW + kp*4) = lo;
    }
  }
  __syncthreads();

  // ---- GEMM2: warp grid M2 x N8, warp tile 32x16 ----
  float acc2[2][2][4];
  #pragma unroll
  for (int mt=0;mt<2;mt++)
    #pragma unroll
    for (int nt=0;nt<2;nt++)
      #pragma unroll
      for (int q=0;q<4;q++) acc2[mt][nt][q] = 0.f;

  const int wm2 = w & 1;          // rows 32*wm2
  const int wn2 = w >> 1;         // cols 16*wn2
  int b2buf = 0;
  #pragma unroll 1
  for (int kt2=0; kt2<NC2; ++kt2){
    float2 pb2[4];
    const bool more2 = (kt2+1 < NC2);
    if (more2){
      const float* Wb = W2e + (size_t)(kt2+1)*32*CDIM;
      int n = w*8 + (lane&7);
      #pragma unroll
      for (int i=0;i<4;i++){
        int kp = i*4 + kp0;
        if (n < CDIM){
          pb2[i].x = Wb[(size_t)(2*kp)*CDIM + n];
          pb2[i].y = Wb[(size_t)(2*kp+1)*CDIM + n];
        } else { pb2[i].x = 0.f; pb2[i].y = 0.f; }
      }
    }
    {
      uint32_t ah[2][2][4], al[2][2][4];
      #pragma unroll
      for (int mt=0;mt<2;mt++)
        #pragma unroll
        for (int kg=0;kg<2;kg++){
          uint32_t ad = smb + A2_OFF + (wm2*32 + mt*16 + (lane&15))*LDA2
                      + kt2*64 + kg*32 + (lane>>4)*16;
          ldsm4(ah[mt][kg], ad);
          ldsm4(al[mt][kg], ad + A2HL);
        }
      const uint32_t Bb = smb + B2_OFF + b2buf*B2BUF;
      #pragma unroll
      for (int nt=0;nt<2;nt++){
        uint32_t ba = Bb + (wn2*16 + nt*8 + (lane&7))*LDW + (lane>>3)*16;
        uint32_t bh[4], bl[4];
        ldsm4(bh, ba);
        ldsm4(bl, ba + B2HL);
        #pragma unroll
        for (int mt=0;mt<2;mt++)
          #pragma unroll
          for (int kg=0;kg<2;kg++){
            mma_bf16(acc2[mt][nt], ah[mt][kg], bh[2*kg], bh[2*kg+1]);
            mma_bf16(acc2[mt][nt], ah[mt][kg], bl[2*kg], bl[2*kg+1]);
            mma_bf16(acc2[mt][nt], al[mt][kg], bh[2*kg], bh[2*kg+1]);
          }
      }
    }
    if (more2){
      int nb = b2buf ^ 1;
      char* Bd = smc + B2_OFF + nb*B2BUF;
      int n = w*8 + (lane&7);
      #pragma unroll
      for (int i=0;i<4;i++){
        int kp = i*4 + kp0;
        uint32_t hi, lo; split2(pb2[i].x, pb2[i].y, hi, lo);
        *(uint32_t*)(Bd + n*LDW + kp*4)        = hi;
        *(uint32_t*)(Bd + B2HL + n*LDW + kp*4) = lo;
      }
      __syncthreads();
      b2buf = nb;
    }
  }

  // ---- epilogue: + b2, scatter ----
  #pragma unroll
  for (int mt=0;mt<2;mt++)
    #pragma unroll
    for (int nt=0;nt<2;nt++)
      #pragma unroll
      for (int q=0;q<4;q++){
        int r = wm2*32 + mt*16 + (lane>>2) + 8*(q>>1);
        int c = wn2*16 + nt*8 + 2*(lane&3) + (q&1);
        if (r < nvalid && c < CDIM)
          out[(size_t)ridx[r]*CDIM + c] = acc2[mt][nt][q] + b2s[c];
      }
}

// ---------------------------------------------------------------------------
extern "C" void kernel_launch(void* const* d_in, const int* in_sizes, int n_in,
                              void* d_out, int out_size){
  (void)in_sizes; (void)n_in; (void)out_size;
  const float* x      = (const float*)d_in[0];
  const float* protos = (const float*)d_in[1];
  const float* gnew   = (const float*)d_in[2];
  const float* gmem   = (const float*)d_in[3];
  const int*   cc     = (const int*)  d_in[4];
  const float* W1     = (const float*)d_in[5];
  const float* b1     = (const float*)d_in[6];
  const float* gamma  = (const float*)d_in[7];
  const float* beta   = (const float*)d_in[8];
  const float* W2     = (const float*)d_in[9];
  const float* b2     = (const float*)d_in[10];
  float* out = (float*)d_out;

  prep_kernel<<<1, 960>>>(protos, gnew, gmem, cc);
  route_kernel<<<BDIM/8, 256>>>(x, protos);
  scatter_kernel<<<BDIM/256, 256>>>();

  cudaFuncSetAttribute(mlp_kernel, cudaFuncAttributeMaxDynamicSharedMemorySize, DYNB);
  mlp_kernel<<<MAXT, NTHR, DYNB>>>(x, W1, b1, gamma, beta, W2, b2, out);
}